// round 1
// baseline (speedup 1.0000x reference)
#include <cuda_runtime.h>
#include <cstdint>

#define TX 32
#define TY 64
#define HALO 5
#define IMG 512
#define IN_W 42                 // TX + 2*HALO
#define IN_H 74                 // TY + 2*HALO
#define IN_STRIDE 43            // conflict-free for phase-2 read pattern
#define H_STRIDE 33             // conflict-free for phase-2 write / phase-3 read
#define NTHREADS 256
#define GRID_X 16
#define GRID_Y 8
#define GRID_Z 96
#define NBLOCKS (GRID_X * GRID_Y * GRID_Z)

#define SSIM_C1 0.0001f
#define SSIM_C2 0.0009f

#define SMEM_FLOATS (2 * IN_H * IN_STRIDE + 4 * IN_H * H_STRIDE)
#define SMEM_BYTES (SMEM_FLOATS * 4)

__device__ float g_partials[NBLOCKS];

// 11-tap Gaussian, sigma=1.5, normalized (computed in double precision offline)
#define GW_INIT {0.00102838f, 0.00759876f, 0.03600077f, 0.10936070f, \
                 0.21300552f, 0.26601174f, 0.21300552f, 0.10936070f, \
                 0.03600077f, 0.00759876f, 0.00102838f}

__global__ __launch_bounds__(NTHREADS)
void ssim_main(const float* __restrict__ img1, const float* __restrict__ img2)
{
    const float W[11] = GW_INIT;

    extern __shared__ float smem[];
    float* ss  = smem;                         // s = x + y, [IN_H][IN_STRIDE]
    float* sd  = ss  + IN_H * IN_STRIDE;       // d = x - y
    float* hs  = sd  + IN_H * IN_STRIDE;       // horiz conv of s,  [IN_H][H_STRIDE]
    float* hd  = hs  + IN_H * H_STRIDE;        // horiz conv of d
    float* hs2 = hd  + IN_H * H_STRIDE;        // horiz conv of s^2
    float* hd2 = hs2 + IN_H * H_STRIDE;        // horiz conv of d^2

    const int t = threadIdx.x;
    const int gx0 = blockIdx.x * TX - HALO;
    const int gy0 = blockIdx.y * TY - HALO;
    const size_t plane = (size_t)blockIdx.z * (IMG * IMG);
    const float* p1 = img1 + plane;
    const float* p2 = img2 + plane;

    // ---------------- Phase 1: load halo tile, form s/d ----------------
    for (int idx = t; idx < IN_W * IN_H; idx += NTHREADS) {
        int r = idx / IN_W;
        int c = idx - r * IN_W;
        int gx = gx0 + c;
        int gy = gy0 + r;
        float a = 0.0f, b = 0.0f;
        if ((unsigned)gx < (unsigned)IMG && (unsigned)gy < (unsigned)IMG) {
            int off = gy * IMG + gx;
            a = p1[off];
            b = p2[off];
        }
        ss[r * IN_STRIDE + c] = a + b;
        sd[r * IN_STRIDE + c] = a - b;
    }
    __syncthreads();

    // ---------------- Phase 2: horizontal conv, 8-output chunks ----------------
    // 74 rows x 4 chunks of 8 cols = 296 tasks
    for (int task = t; task < IN_H * 4; task += NTHREADS) {
        int r  = task >> 2;
        int jb = (task & 3) << 3;
        int ib = r * IN_STRIDE + jb;
        int ob = r * H_STRIDE + jb;

        // s / s^2 pass
        {
            float v[18], v2[18];
            #pragma unroll
            for (int i = 0; i < 18; i++) { v[i] = ss[ib + i]; v2[i] = v[i] * v[i]; }
            float a[8], a2[8];
            #pragma unroll
            for (int j = 0; j < 8; j++) { a[j] = 0.0f; a2[j] = 0.0f; }
            #pragma unroll
            for (int k = 0; k < 11; k++) {
                float wk = W[k];
                #pragma unroll
                for (int j = 0; j < 8; j++) {
                    a[j]  += wk * v[j + k];
                    a2[j] += wk * v2[j + k];
                }
            }
            #pragma unroll
            for (int j = 0; j < 8; j++) { hs[ob + j] = a[j]; hs2[ob + j] = a2[j]; }
        }
        // d / d^2 pass
        {
            float v[18], v2[18];
            #pragma unroll
            for (int i = 0; i < 18; i++) { v[i] = sd[ib + i]; v2[i] = v[i] * v[i]; }
            float a[8], a2[8];
            #pragma unroll
            for (int j = 0; j < 8; j++) { a[j] = 0.0f; a2[j] = 0.0f; }
            #pragma unroll
            for (int k = 0; k < 11; k++) {
                float wk = W[k];
                #pragma unroll
                for (int j = 0; j < 8; j++) {
                    a[j]  += wk * v[j + k];
                    a2[j] += wk * v2[j + k];
                }
            }
            #pragma unroll
            for (int j = 0; j < 8; j++) { hd[ob + j] = a[j]; hd2[ob + j] = a2[j]; }
        }
    }
    __syncthreads();

    // ---------------- Phase 3: vertical conv (8 rows/thread) + epilogue ----------------
    const int col = t & 31;
    const int r0  = (t >> 5) << 3;

    float Ms[8], Md[8], Es[8], Ed[8];
    {
        float v[18];
        #pragma unroll
        for (int k = 0; k < 18; k++) v[k] = hs[(r0 + k) * H_STRIDE + col];
        #pragma unroll
        for (int o = 0; o < 8; o++) {
            float a = 0.0f;
            #pragma unroll
            for (int k = 0; k < 11; k++) a += W[k] * v[o + k];
            Ms[o] = a;
        }
        #pragma unroll
        for (int k = 0; k < 18; k++) v[k] = hd[(r0 + k) * H_STRIDE + col];
        #pragma unroll
        for (int o = 0; o < 8; o++) {
            float a = 0.0f;
            #pragma unroll
            for (int k = 0; k < 11; k++) a += W[k] * v[o + k];
            Md[o] = a;
        }
        #pragma unroll
        for (int k = 0; k < 18; k++) v[k] = hs2[(r0 + k) * H_STRIDE + col];
        #pragma unroll
        for (int o = 0; o < 8; o++) {
            float a = 0.0f;
            #pragma unroll
            for (int k = 0; k < 11; k++) a += W[k] * v[o + k];
            Es[o] = a;
        }
        #pragma unroll
        for (int k = 0; k < 18; k++) v[k] = hd2[(r0 + k) * H_STRIDE + col];
        #pragma unroll
        for (int o = 0; o < 8; o++) {
            float a = 0.0f;
            #pragma unroll
            for (int k = 0; k < 11; k++) a += W[k] * v[o + k];
            Ed[o] = a;
        }
    }

    float lsum = 0.0f;
    #pragma unroll
    for (int o = 0; o < 8; o++) {
        float ms = Ms[o], md = Md[o], es = Es[o], ed = Ed[o];
        float ms2 = ms * ms, md2 = md * md;
        float mu12  = 0.25f * (ms2 - md2);           // mu1*mu2
        float musq  = 0.5f  * (ms2 + md2);           // mu1^2 + mu2^2
        float s12x2 = 0.5f  * (es - ed) - 2.0f * mu12;  // 2*sigma12
        float ssum  = 0.5f  * (es + ed) - musq;         // sigma1^2 + sigma2^2
        float num = (2.0f * mu12 + SSIM_C1) * (s12x2 + SSIM_C2);
        float den = (musq + SSIM_C1) * (ssum + SSIM_C2);
        float v = __fdividef(num, den);
        v = fminf(fmaxf(v, 0.0f), 1.0f);
        lsum += v;
    }

    // ---------------- Block reduction ----------------
    #pragma unroll
    for (int off = 16; off > 0; off >>= 1)
        lsum += __shfl_down_sync(0xffffffffu, lsum, off);

    __syncthreads();   // phase-3 smem reads done; reuse ss[] region
    if ((t & 31) == 0) ss[t >> 5] = lsum;
    __syncthreads();
    if (t == 0) {
        float tot = 0.0f;
        #pragma unroll
        for (int w = 0; w < 8; w++) tot += ss[w];
        g_partials[(blockIdx.z * GRID_Y + blockIdx.y) * GRID_X + blockIdx.x] = tot;
    }
}

__global__ void ssim_reduce(float* __restrict__ out)
{
    __shared__ double rb[NTHREADS];
    double acc = 0.0;
    for (int i = threadIdx.x; i < NBLOCKS; i += NTHREADS)
        acc += (double)g_partials[i];
    rb[threadIdx.x] = acc;
    __syncthreads();
    for (int s = NTHREADS / 2; s > 0; s >>= 1) {
        if (threadIdx.x < s) rb[threadIdx.x] += rb[threadIdx.x + s];
        __syncthreads();
    }
    if (threadIdx.x == 0)
        out[0] = (float)(1.0 - rb[0] / (double)(32.0 * 3.0 * 512.0 * 512.0));
}

extern "C" void kernel_launch(void* const* d_in, const int* in_sizes, int n_in,
                              void* d_out, int out_size)
{
    const float* img1 = (const float*)d_in[0];
    const float* img2 = (const float*)d_in[1];

    cudaFuncSetAttribute(ssim_main,
                         cudaFuncAttributeMaxDynamicSharedMemorySize, SMEM_BYTES);

    dim3 grid(GRID_X, GRID_Y, GRID_Z);
    ssim_main<<<grid, NTHREADS, SMEM_BYTES>>>(img1, img2);
    ssim_reduce<<<1, NTHREADS>>>((float*)d_out);
}